// round 1
// baseline (speedup 1.0000x reference)
#include <cuda_runtime.h>
#include <math.h>
#include <float.h>

// Problem constants
#define GH   16        // B*H groups
#define SEQ  2048
#define EMB  512
#define DH   64
#define MR   4096      // B*S rows
#define MLPD 2048

// ---------------- scratch (static device globals; no allocation) ----------------
__device__ float g_nq [MR*EMB];
__device__ float g_q  [MR*EMB];
__device__ float g_k  [MR*EMB];
__device__ float g_v  [MR*EMB];
__device__ float g_W  [(size_t)GH*SEQ*SEQ];     // 256MB: scores -> exp(p) in place
__device__ float g_rsum[GH*SEQ];
__device__ float g_rmax[GH*SEQ];
__device__ float g_rmin[GH*SEQ];
__device__ float g_Z  [GH*SEQ];
__device__ float g_O  [GH*SEQ*DH];
__device__ float g_Oc [MR*EMB];
__device__ float g_x  [MR*EMB];
__device__ float g_h  [MR*EMB];
__device__ float g_mlp[(size_t)MR*MLPD];

// ---------------- helpers ----------------
__device__ __forceinline__ void atomicMaxF(float* addr, float val) {
    int old = __float_as_int(*addr);
    while (__int_as_float(old) < val) {
        int assumed = old;
        old = atomicCAS((int*)addr, assumed, __float_as_int(val));
        if (old == assumed) break;
    }
}
__device__ __forceinline__ void atomicMinF(float* addr, float val) {
    int old = __float_as_int(*addr);
    while (__int_as_float(old) > val) {
        int assumed = old;
        old = atomicCAS((int*)addr, assumed, __float_as_int(val));
        if (old == assumed) break;
    }
}

// ---------------- LayerNorm (1 block / row of 512) ----------------
__global__ void ln_kernel(const float* __restrict__ x, const float* __restrict__ w,
                          const float* __restrict__ b, float* __restrict__ y) {
    int row = blockIdx.x;
    const float* xr = x + (size_t)row * EMB;
    int t = threadIdx.x;
    float v0 = xr[t], v1 = xr[t + 256];
    float s = v0 + v1, q = v0 * v0 + v1 * v1;
#pragma unroll
    for (int off = 16; off; off >>= 1) {
        s += __shfl_xor_sync(~0u, s, off);
        q += __shfl_xor_sync(~0u, q, off);
    }
    __shared__ float ss[8], sq[8];
    if ((t & 31) == 0) { ss[t >> 5] = s; sq[t >> 5] = q; }
    __syncthreads();
    if (t == 0) {
        float s2 = 0.f, q2 = 0.f;
#pragma unroll
        for (int i = 0; i < 8; i++) { s2 += ss[i]; q2 += sq[i]; }
        ss[0] = s2; sq[0] = q2;
    }
    __syncthreads();
    float mean = ss[0] * (1.f / EMB);
    float var  = sq[0] * (1.f / EMB) - mean * mean;
    float rstd = rsqrtf(var + 1e-5f);
    float* yr = y + (size_t)row * EMB;
    yr[t]       = (v0 - mean) * rstd * w[t]       + b[t];
    yr[t + 256] = (v1 - mean) * rstd * w[t + 256] + b[t + 256];
}

// ---------------- generic tiled SGEMM:  C[m,n] = sum_k A[m,k]*B[n,k] (+ epilogue) ----
// EPI 0: qkv split store (bias); EPI 1: bias + residual add; EPI 2: bias + exact gelu
template <int EPI>
__global__ void sgemm_nt(const float* __restrict__ A, const float* __restrict__ B,
                         const float* __restrict__ bias, const float* __restrict__ res,
                         float* __restrict__ C0, float* __restrict__ C1, float* __restrict__ C2,
                         int M, int N, int K) {
    __shared__ __align__(16) float As[16][64];
    __shared__ __align__(16) float Bs[16][64];
    const int tx = threadIdx.x & 15, ty = threadIdx.x >> 4;
    const int m0 = blockIdx.y << 6, n0 = blockIdx.x << 6;
    const int lr = threadIdx.x >> 2;        // 0..63
    const int lc = (threadIdx.x & 3) << 2;  // 0,4,8,12
    const float* Ap = A + (size_t)(m0 + lr) * K + lc;
    const float* Bp = B + (size_t)(n0 + lr) * K + lc;
    float acc[4][4] = {};
    for (int k0 = 0; k0 < K; k0 += 16) {
        float4 av = *(const float4*)(Ap + k0);
        float4 bv = *(const float4*)(Bp + k0);
        __syncthreads();
        As[lc + 0][lr] = av.x; As[lc + 1][lr] = av.y; As[lc + 2][lr] = av.z; As[lc + 3][lr] = av.w;
        Bs[lc + 0][lr] = bv.x; Bs[lc + 1][lr] = bv.y; Bs[lc + 2][lr] = bv.z; Bs[lc + 3][lr] = bv.w;
        __syncthreads();
#pragma unroll
        for (int k = 0; k < 16; k++) {
            float4 a = *(const float4*)&As[k][ty << 2];
            float4 b = *(const float4*)&Bs[k][tx << 2];
            float aa[4] = {a.x, a.y, a.z, a.w};
            float bb[4] = {b.x, b.y, b.z, b.w};
#pragma unroll
            for (int i = 0; i < 4; i++)
#pragma unroll
                for (int j = 0; j < 4; j++) acc[i][j] += aa[i] * bb[j];
        }
    }
#pragma unroll
    for (int i = 0; i < 4; i++) {
        int row = m0 + (ty << 2) + i;
#pragma unroll
        for (int j = 0; j < 4; j++) {
            int col = n0 + (tx << 2) + j;
            float v = acc[i][j] + bias[col];
            if (EPI == 0) {
                float* dst = (col < 512) ? C0 : ((col < 1024) ? C1 : C2);
                dst[(size_t)row * 512 + (col & 511)] = v;
            } else if (EPI == 1) {
                C0[(size_t)row * N + col] = v + res[(size_t)row * N + col];
            } else {
                C0[(size_t)row * N + col] = 0.5f * v * (1.f + erff(v * 0.7071067811865475f));
            }
        }
    }
}

// ---------------- scores: W = (Q K^T) * gate, track per-row sum/min/max -----------
__global__ void scores_kernel(const float* __restrict__ Q, const float* __restrict__ Km,
                              const float* __restrict__ gate, float* __restrict__ W,
                              float* __restrict__ rsum, float* __restrict__ rmax,
                              float* __restrict__ rmin) {
    const int g = blockIdx.z;
    const int i0 = blockIdx.y << 6, j0 = blockIdx.x << 6;
    __shared__ __align__(16) float Qs[64][64];
    __shared__ __align__(16) float Ks[64][64];
    const float* Qg = Q + (size_t)g * SEQ * DH;
    const float* Kg = Km + (size_t)g * SEQ * DH;
#pragma unroll
    for (int it = 0; it < 4; it++) {
        int idx = threadIdx.x + (it << 8);
        int row = idx >> 4, cc = (idx & 15) << 2;
        float4 qv = *(const float4*)&Qg[(size_t)(i0 + row) * DH + cc];
        float4 kv = *(const float4*)&Kg[(size_t)(j0 + row) * DH + cc];
        Qs[cc + 0][row] = qv.x; Qs[cc + 1][row] = qv.y; Qs[cc + 2][row] = qv.z; Qs[cc + 3][row] = qv.w;
        Ks[cc + 0][row] = kv.x; Ks[cc + 1][row] = kv.y; Ks[cc + 2][row] = kv.z; Ks[cc + 3][row] = kv.w;
    }
    __syncthreads();
    const int tx = threadIdx.x & 15, ty = threadIdx.x >> 4;
    float acc[4][4] = {};
#pragma unroll 8
    for (int d = 0; d < 64; d++) {
        float4 a = *(const float4*)&Qs[d][ty << 2];
        float4 b = *(const float4*)&Ks[d][tx << 2];
        float aa[4] = {a.x, a.y, a.z, a.w};
        float bb[4] = {b.x, b.y, b.z, b.w};
#pragma unroll
        for (int i = 0; i < 4; i++)
#pragma unroll
            for (int j = 0; j < 4; j++) acc[i][j] += aa[i] * bb[j];
    }
    float rs[4], mx[4], mn[4];
    size_t wbase = (size_t)g * SEQ * SEQ;
#pragma unroll
    for (int i = 0; i < 4; i++) {
        int row = i0 + (ty << 2) + i;
        size_t off = wbase + (size_t)row * SEQ + j0 + (tx << 2);
        float4 gt = *(const float4*)&gate[off];
        float v0 = acc[i][0] * gt.x, v1 = acc[i][1] * gt.y;
        float v2 = acc[i][2] * gt.z, v3 = acc[i][3] * gt.w;
        float4 wv = make_float4(v0, v1, v2, v3);
        *(float4*)&W[off] = wv;
        rs[i] = v0 + v1 + v2 + v3;
        mx[i] = fmaxf(fmaxf(v0, v1), fmaxf(v2, v3));
        mn[i] = fminf(fminf(v0, v1), fminf(v2, v3));
    }
#pragma unroll
    for (int off = 8; off; off >>= 1) {
#pragma unroll
        for (int i = 0; i < 4; i++) {
            rs[i] += __shfl_xor_sync(~0u, rs[i], off);
            mx[i] = fmaxf(mx[i], __shfl_xor_sync(~0u, mx[i], off));
            mn[i] = fminf(mn[i], __shfl_xor_sync(~0u, mn[i], off));
        }
    }
    if (tx == 0) {
#pragma unroll
        for (int i = 0; i < 4; i++) {
            int row = g * SEQ + i0 + (ty << 2) + i;
            atomicAdd(&rsum[row], rs[i]);
            atomicMaxF(&rmax[row], mx[i]);
            atomicMinF(&rmin[row], mn[i]);
        }
    }
}

__global__ void init_stats(float* rsum, float* rmax, float* rmin) {
    int i = blockIdx.x * blockDim.x + threadIdx.x;
    if (i < GH * SEQ) { rsum[i] = 0.f; rmax[i] = -FLT_MAX; rmin[i] = FLT_MAX; }
}

// ---------------- exp pass: W <- exp(W/s - m), per-row Z ----------------
__global__ void softmax_exp_kernel(float* __restrict__ W, const float* __restrict__ rsum,
                                   const float* __restrict__ rmax, const float* __restrict__ rmin,
                                   float* __restrict__ Z) {
    int row = blockIdx.x;
    float s = rsum[row] + 1e-12f;
    float inv = 1.f / s;
    float m = (s > 0.f) ? rmax[row] * inv : rmin[row] * inv;
    float* Wr = W + (size_t)row * SEQ;
    float z = 0.f;
#pragma unroll
    for (int k = 0; k < 8; k++) {
        int j = threadIdx.x + (k << 8);
        float p = expf(Wr[j] * inv - m);
        Wr[j] = p;
        z += p;
    }
#pragma unroll
    for (int off = 16; off; off >>= 1) z += __shfl_xor_sync(~0u, z, off);
    __shared__ float sm[8];
    if ((threadIdx.x & 31) == 0) sm[threadIdx.x >> 5] = z;
    __syncthreads();
    if (threadIdx.x == 0) {
        float t = 0.f;
#pragma unroll
        for (int i = 0; i < 8; i++) t += sm[i];
        Z[row] = t;
    }
}

// ---------------- head-averaged attn weights out ----------------
__global__ void avgw_kernel(const float* __restrict__ P, const float* __restrict__ Z,
                            float* __restrict__ out) {
    int i = blockIdx.x, b = blockIdx.y;
    float iz[8];
#pragma unroll
    for (int h = 0; h < 8; h++) iz[h] = 0.125f / Z[(b * 8 + h) * SEQ + i];
    size_t obase = (size_t)b * SEQ * SEQ + (size_t)i * SEQ;
#pragma unroll
    for (int k = 0; k < 8; k++) {
        int j = threadIdx.x + (k << 8);
        float a = 0.f;
#pragma unroll
        for (int h = 0; h < 8; h++)
            a += P[(size_t)(b * 8 + h) * SEQ * SEQ + (size_t)i * SEQ + j] * iz[h];
        out[obase + j] = a;
    }
}

// ---------------- O = (P @ V) * invZ  (per group; N=64 full) ----------------
__global__ void pv_kernel(const float* __restrict__ P, const float* __restrict__ V,
                          const float* __restrict__ Z, float* __restrict__ O) {
    int g = blockIdx.y;
    int m0 = blockIdx.x << 6;
    __shared__ __align__(16) float Ps[32][64];
    __shared__ __align__(16) float Vs[32][64];
    const float* Pg = P + (size_t)g * SEQ * SEQ;
    const float* Vg = V + (size_t)g * SEQ * DH;
    const int tx = threadIdx.x & 15, ty = threadIdx.x >> 4;
    float acc[4][4] = {};
    for (int k0 = 0; k0 < SEQ; k0 += 32) {
        __syncthreads();
#pragma unroll
        for (int it = 0; it < 2; it++) {
            int idx = threadIdx.x + (it << 8);
            int pr = idx >> 3, pc = (idx & 7) << 2;
            float4 pv = *(const float4*)&Pg[(size_t)(m0 + pr) * SEQ + k0 + pc];
            Ps[pc + 0][pr] = pv.x; Ps[pc + 1][pr] = pv.y; Ps[pc + 2][pr] = pv.z; Ps[pc + 3][pr] = pv.w;
            int vr = idx >> 4, vc = (idx & 15) << 2;
            float4 vv = *(const float4*)&Vg[(size_t)(k0 + vr) * DH + vc];
            *(float4*)&Vs[vr][vc] = vv;
        }
        __syncthreads();
#pragma unroll 8
        for (int k = 0; k < 32; k++) {
            float4 a = *(const float4*)&Ps[k][ty << 2];
            float4 b = *(const float4*)&Vs[k][tx << 2];
            float aa[4] = {a.x, a.y, a.z, a.w};
            float bb[4] = {b.x, b.y, b.z, b.w};
#pragma unroll
            for (int i = 0; i < 4; i++)
#pragma unroll
                for (int j = 0; j < 4; j++) acc[i][j] += aa[i] * bb[j];
        }
    }
#pragma unroll
    for (int i = 0; i < 4; i++) {
        int row = m0 + (ty << 2) + i;
        float izv = 1.f / Z[g * SEQ + row];
#pragma unroll
        for (int j = 0; j < 4; j++)
            O[(size_t)g * SEQ * DH + (size_t)row * DH + (tx << 2) + j] = acc[i][j] * izv;
    }
}

// ---------------- gather: Oc[b,s,e] = O[b*8 + e/64, s, e%64] ----------------
__global__ void gather_kernel(const float* __restrict__ O, float* __restrict__ Oc) {
    int idx = blockIdx.x * blockDim.x + threadIdx.x;  // < 2097152
    int e = idx & 511;
    int s = (idx >> 9) & 2047;
    int b = idx >> 20;
    Oc[idx] = O[(size_t)(b * 8 + (e >> 6)) * SEQ * DH + (size_t)s * DH + (e & 63)];
}

// ---------------- launcher ----------------
extern "C" void kernel_launch(void* const* d_in, const int* in_sizes, int n_in,
                              void* d_out, int out_size) {
    const float* query = (const float*)d_in[0];
    const float* gate  = (const float*)d_in[1];
    const float* ipw   = (const float*)d_in[2];
    const float* ipb   = (const float*)d_in[3];
    const float* outw  = (const float*)d_in[4];
    const float* outb  = (const float*)d_in[5];
    const float* ln1w  = (const float*)d_in[6];
    const float* ln1b  = (const float*)d_in[7];
    const float* ln2w  = (const float*)d_in[8];
    const float* ln2b  = (const float*)d_in[9];
    const float* w1    = (const float*)d_in[10];
    const float* b1    = (const float*)d_in[11];
    const float* w2    = (const float*)d_in[12];
    const float* b2    = (const float*)d_in[13];
    float* out_x = (float*)d_out;
    float* out_w = out_x + (size_t)2 * SEQ * EMB;

    float *p_nq, *p_q, *p_k, *p_v, *p_W, *p_rsum, *p_rmax, *p_rmin, *p_Z;
    float *p_O, *p_Oc, *p_x, *p_h, *p_mlp;
    cudaGetSymbolAddress((void**)&p_nq,  g_nq);
    cudaGetSymbolAddress((void**)&p_q,   g_q);
    cudaGetSymbolAddress((void**)&p_k,   g_k);
    cudaGetSymbolAddress((void**)&p_v,   g_v);
    cudaGetSymbolAddress((void**)&p_W,   g_W);
    cudaGetSymbolAddress((void**)&p_rsum,g_rsum);
    cudaGetSymbolAddress((void**)&p_rmax,g_rmax);
    cudaGetSymbolAddress((void**)&p_rmin,g_rmin);
    cudaGetSymbolAddress((void**)&p_Z,   g_Z);
    cudaGetSymbolAddress((void**)&p_O,   g_O);
    cudaGetSymbolAddress((void**)&p_Oc,  g_Oc);
    cudaGetSymbolAddress((void**)&p_x,   g_x);
    cudaGetSymbolAddress((void**)&p_h,   g_h);
    cudaGetSymbolAddress((void**)&p_mlp, g_mlp);

    // 0) stats init
    init_stats<<<(GH * SEQ + 255) / 256, 256>>>(p_rsum, p_rmax, p_rmin);
    // 1) LN1
    ln_kernel<<<MR, 256>>>(query, ln1w, ln1b, p_nq);
    // 2) QKV projection (split store)
    sgemm_nt<0><<<dim3(24, 64), 256>>>(p_nq, ipw, ipb, nullptr, p_q, p_k, p_v, MR, 1536, EMB);
    // 3) scores * gate + row stats
    scores_kernel<<<dim3(32, 32, GH), 256>>>(p_q, p_k, gate, p_W, p_rsum, p_rmax, p_rmin);
    // 4) exp pass (in place) + Z
    softmax_exp_kernel<<<GH * SEQ, 256>>>(p_W, p_rsum, p_rmax, p_rmin, p_Z);
    // 5) head-averaged attention weights -> second output
    avgw_kernel<<<dim3(SEQ, 2), 256>>>(p_W, p_Z, out_w);
    // 6) O = softmax @ V
    pv_kernel<<<dim3(32, GH), 256>>>(p_W, p_v, p_Z, p_O);
    // 7) gather to (B,S,E) layout
    gather_kernel<<<MR * EMB / 256, 256>>>(p_O, p_Oc);
    // 8) out projection + residual (query)
    sgemm_nt<1><<<dim3(8, 64), 256>>>(p_Oc, outw, outb, query, p_x, nullptr, nullptr, MR, EMB, EMB);
    // 9) LN2
    ln_kernel<<<MR, 256>>>(p_x, ln2w, ln2b, p_h);
    // 10) MLP up + exact GELU
    sgemm_nt<2><<<dim3(32, 64), 256>>>(p_h, w1, b1, nullptr, p_mlp, nullptr, nullptr, MR, MLPD, EMB);
    // 11) MLP down + residual -> first output
    sgemm_nt<1><<<dim3(8, 64), 256>>>(p_mlp, w2, b2, p_x, out_x, nullptr, nullptr, MR, EMB, MLPD);
}

// round 2
// speedup vs baseline: 1.4298x; 1.4298x over previous
#include <cuda_runtime.h>
#include <math.h>
#include <float.h>

// Problem constants
#define GH   16        // B*H groups
#define SEQ  2048
#define EMB  512
#define DH   64
#define MR   4096      // B*S rows
#define MLPD 2048

typedef unsigned long long u64;

// ---------------- scratch (static device globals; no allocation) ----------------
__device__ float g_nq [MR*EMB];
__device__ float g_q  [MR*EMB];
__device__ float g_k  [MR*EMB];
__device__ float g_v  [MR*EMB];
__device__ float g_W  [(size_t)GH*SEQ*SEQ];     // 256MB: scores -> exp(p) in place
__device__ float g_rsum[GH*SEQ];
__device__ float g_rmax[GH*SEQ];
__device__ float g_rmin[GH*SEQ];
__device__ float g_Z  [GH*SEQ];
__device__ float g_Oc [MR*EMB];
__device__ float g_x  [MR*EMB];
__device__ float g_h  [MR*EMB];
__device__ float g_mlp[(size_t)MR*MLPD];

// ---------------- packed f32x2 helpers ----------------
__device__ __forceinline__ u64 dup2(float a) {
    u64 r; asm("mov.b64 %0, {%1,%1};" : "=l"(r) : "f"(a)); return r;
}
__device__ __forceinline__ void ffma2(u64& d, u64 a, u64 b) {
    asm("fma.rn.f32x2 %0, %1, %2, %0;" : "+l"(d) : "l"(a), "l"(b));
}
__device__ __forceinline__ float2 unp(u64 v) {
    float2 r; asm("mov.b64 {%0,%1}, %2;" : "=f"(r.x), "=f"(r.y) : "l"(v)); return r;
}

__device__ __forceinline__ void atomicMaxF(float* addr, float val) {
    int old = __float_as_int(*addr);
    while (__int_as_float(old) < val) {
        int assumed = old;
        old = atomicCAS((int*)addr, assumed, __float_as_int(val));
        if (old == assumed) break;
    }
}
__device__ __forceinline__ void atomicMinF(float* addr, float val) {
    int old = __float_as_int(*addr);
    while (__int_as_float(old) > val) {
        int assumed = old;
        old = atomicCAS((int*)addr, assumed, __float_as_int(val));
        if (old == assumed) break;
    }
}

// ---------------- LayerNorm (1 block / row of 512) ----------------
__global__ void ln_kernel(const float* __restrict__ x, const float* __restrict__ w,
                          const float* __restrict__ b, float* __restrict__ y) {
    int row = blockIdx.x;
    const float* xr = x + (size_t)row * EMB;
    int t = threadIdx.x;
    float v0 = xr[t], v1 = xr[t + 256];
    float s = v0 + v1, q = v0 * v0 + v1 * v1;
#pragma unroll
    for (int off = 16; off; off >>= 1) {
        s += __shfl_xor_sync(~0u, s, off);
        q += __shfl_xor_sync(~0u, q, off);
    }
    __shared__ float ss[8], sq[8];
    if ((t & 31) == 0) { ss[t >> 5] = s; sq[t >> 5] = q; }
    __syncthreads();
    if (t == 0) {
        float s2 = 0.f, q2 = 0.f;
#pragma unroll
        for (int i = 0; i < 8; i++) { s2 += ss[i]; q2 += sq[i]; }
        ss[0] = s2; sq[0] = q2;
    }
    __syncthreads();
    float mean = ss[0] * (1.f / EMB);
    float var  = sq[0] * (1.f / EMB) - mean * mean;
    float rstd = rsqrtf(var + 1e-5f);
    float* yr = y + (size_t)row * EMB;
    yr[t]       = (v0 - mean) * rstd * w[t]       + b[t];
    yr[t + 256] = (v1 - mean) * rstd * w[t + 256] + b[t + 256];
}

// ======== 128x128x16 SGEMM, 8x8 microtile, packed FFMA2 ========
// C[m,n] = sum_k A[m,k] * B[n,k] + bias[n]  (+ epilogue)
// EPI 0: qkv split store; EPI 1: + residual; EPI 2: exact gelu
template <int EPI>
__global__ __launch_bounds__(256, 2)
void sgemm128(const float* __restrict__ A, const float* __restrict__ B,
              const float* __restrict__ bias, const float* __restrict__ res,
              float* __restrict__ C0, float* __restrict__ C1, float* __restrict__ C2,
              int M, int N, int K) {
    __shared__ __align__(16) float As[16][132];
    __shared__ __align__(16) float Bs[16][132];
    const int tid = threadIdx.x;
    const int tx = tid & 15, ty = tid >> 4;
    const int m0 = blockIdx.y << 7, n0 = blockIdx.x << 7;
    const int lr = tid >> 2;            // 0..63
    const int lc = (tid & 3) << 2;      // 0,4,8,12
    const float* Ap0 = A + (size_t)(m0 + lr) * K + lc;
    const float* Ap1 = A + (size_t)(m0 + 64 + lr) * K + lc;
    const float* Bp0 = B + (size_t)(n0 + lr) * K + lc;
    const float* Bp1 = B + (size_t)(n0 + 64 + lr) * K + lc;
    u64 acc[8][4];
#pragma unroll
    for (int i = 0; i < 8; i++)
#pragma unroll
        for (int j = 0; j < 4; j++) acc[i][j] = 0ull;

    for (int k0 = 0; k0 < K; k0 += 16) {
        float4 a0 = *(const float4*)(Ap0 + k0);
        float4 a1 = *(const float4*)(Ap1 + k0);
        float4 b0 = *(const float4*)(Bp0 + k0);
        float4 b1 = *(const float4*)(Bp1 + k0);
        __syncthreads();
        As[lc + 0][lr] = a0.x; As[lc + 1][lr] = a0.y; As[lc + 2][lr] = a0.z; As[lc + 3][lr] = a0.w;
        As[lc + 0][64 + lr] = a1.x; As[lc + 1][64 + lr] = a1.y; As[lc + 2][64 + lr] = a1.z; As[lc + 3][64 + lr] = a1.w;
        Bs[lc + 0][lr] = b0.x; Bs[lc + 1][lr] = b0.y; Bs[lc + 2][lr] = b0.z; Bs[lc + 3][lr] = b0.w;
        Bs[lc + 0][64 + lr] = b1.x; Bs[lc + 1][64 + lr] = b1.y; Bs[lc + 2][64 + lr] = b1.z; Bs[lc + 3][64 + lr] = b1.w;
        __syncthreads();
#pragma unroll
        for (int k = 0; k < 16; k++) {
            float4 af0 = *(const float4*)&As[k][ty << 2];
            float4 af1 = *(const float4*)&As[k][64 + (ty << 2)];
            ulonglong2 bp0 = *(const ulonglong2*)&Bs[k][tx << 2];
            ulonglong2 bp1 = *(const ulonglong2*)&Bs[k][64 + (tx << 2)];
            u64 ad[8] = { dup2(af0.x), dup2(af0.y), dup2(af0.z), dup2(af0.w),
                          dup2(af1.x), dup2(af1.y), dup2(af1.z), dup2(af1.w) };
            u64 bb[4] = { bp0.x, bp0.y, bp1.x, bp1.y };
#pragma unroll
            for (int i = 0; i < 8; i++) {
                ffma2(acc[i][0], ad[i], bb[0]);
                ffma2(acc[i][1], ad[i], bb[1]);
                ffma2(acc[i][2], ad[i], bb[2]);
                ffma2(acc[i][3], ad[i], bb[3]);
            }
        }
    }
#pragma unroll
    for (int i = 0; i < 8; i++) {
        int row = m0 + (ty << 2) + (i & 3) + ((i >> 2) << 6);
#pragma unroll
        for (int jj = 0; jj < 4; jj++) {
            float2 v2 = unp(acc[i][jj]);
            int col = n0 + (tx << 2) + ((jj & 1) << 1) + ((jj >> 1) << 6);
            float vv[2] = { v2.x, v2.y };
#pragma unroll
            for (int u = 0; u < 2; u++) {
                int c = col + u;
                float v = vv[u] + bias[c];
                if (EPI == 0) {
                    float* dst = (c < 512) ? C0 : ((c < 1024) ? C1 : C2);
                    dst[(size_t)row * 512 + (c & 511)] = v;
                } else if (EPI == 1) {
                    C0[(size_t)row * N + c] = v + res[(size_t)row * N + c];
                } else {
                    C0[(size_t)row * N + c] = 0.5f * v * (1.f + erff(v * 0.7071067811865475f));
                }
            }
        }
    }
}

// ======== scores: W = (Q K^T) * gate, 128x128 tile, FFMA2, row stats ========
__global__ __launch_bounds__(256, 2)
void scores_kernel(const float* __restrict__ Q, const float* __restrict__ Km,
                   const float* __restrict__ gate, float* __restrict__ W,
                   float* __restrict__ rsum, float* __restrict__ rmax,
                   float* __restrict__ rmin) {
    __shared__ __align__(16) float As[16][132];
    __shared__ __align__(16) float Bs[16][132];
    const int g = blockIdx.z;
    const int tid = threadIdx.x;
    const int tx = tid & 15, ty = tid >> 4;
    const int i0 = blockIdx.y << 7, j0 = blockIdx.x << 7;
    const int lr = tid >> 2;
    const int lc = (tid & 3) << 2;
    const float* Qg = Q + (size_t)g * SEQ * DH;
    const float* Kg = Km + (size_t)g * SEQ * DH;
    const float* Ap0 = Qg + (size_t)(i0 + lr) * DH + lc;
    const float* Ap1 = Qg + (size_t)(i0 + 64 + lr) * DH + lc;
    const float* Bp0 = Kg + (size_t)(j0 + lr) * DH + lc;
    const float* Bp1 = Kg + (size_t)(j0 + 64 + lr) * DH + lc;
    u64 acc[8][4];
#pragma unroll
    for (int i = 0; i < 8; i++)
#pragma unroll
        for (int j = 0; j < 4; j++) acc[i][j] = 0ull;

    for (int k0 = 0; k0 < DH; k0 += 16) {
        float4 a0 = *(const float4*)(Ap0 + k0);
        float4 a1 = *(const float4*)(Ap1 + k0);
        float4 b0 = *(const float4*)(Bp0 + k0);
        float4 b1 = *(const float4*)(Bp1 + k0);
        __syncthreads();
        As[lc + 0][lr] = a0.x; As[lc + 1][lr] = a0.y; As[lc + 2][lr] = a0.z; As[lc + 3][lr] = a0.w;
        As[lc + 0][64 + lr] = a1.x; As[lc + 1][64 + lr] = a1.y; As[lc + 2][64 + lr] = a1.z; As[lc + 3][64 + lr] = a1.w;
        Bs[lc + 0][lr] = b0.x; Bs[lc + 1][lr] = b0.y; Bs[lc + 2][lr] = b0.z; Bs[lc + 3][lr] = b0.w;
        Bs[lc + 0][64 + lr] = b1.x; Bs[lc + 1][64 + lr] = b1.y; Bs[lc + 2][64 + lr] = b1.z; Bs[lc + 3][64 + lr] = b1.w;
        __syncthreads();
#pragma unroll
        for (int k = 0; k < 16; k++) {
            float4 af0 = *(const float4*)&As[k][ty << 2];
            float4 af1 = *(const float4*)&As[k][64 + (ty << 2)];
            ulonglong2 bp0 = *(const ulonglong2*)&Bs[k][tx << 2];
            ulonglong2 bp1 = *(const ulonglong2*)&Bs[k][64 + (tx << 2)];
            u64 ad[8] = { dup2(af0.x), dup2(af0.y), dup2(af0.z), dup2(af0.w),
                          dup2(af1.x), dup2(af1.y), dup2(af1.z), dup2(af1.w) };
            u64 bb[4] = { bp0.x, bp0.y, bp1.x, bp1.y };
#pragma unroll
            for (int i = 0; i < 8; i++) {
                ffma2(acc[i][0], ad[i], bb[0]);
                ffma2(acc[i][1], ad[i], bb[1]);
                ffma2(acc[i][2], ad[i], bb[2]);
                ffma2(acc[i][3], ad[i], bb[3]);
            }
        }
    }

    float rs[8], mx[8], mn[8];
    size_t wbase = (size_t)g * SEQ * SEQ;
#pragma unroll
    for (int i = 0; i < 8; i++) {
        int row = i0 + (ty << 2) + (i & 3) + ((i >> 2) << 6);
        float2 p0 = unp(acc[i][0]), p1 = unp(acc[i][1]);
        float2 p2 = unp(acc[i][2]), p3 = unp(acc[i][3]);
        size_t offA = wbase + (size_t)row * SEQ + j0 + (tx << 2);
        size_t offB = offA + 64;
        float4 gA = *(const float4*)&gate[offA];
        float4 gB = *(const float4*)&gate[offB];
        float w0 = p0.x * gA.x, w1 = p0.y * gA.y, w2 = p1.x * gA.z, w3 = p1.y * gA.w;
        float w4 = p2.x * gB.x, w5 = p2.y * gB.y, w6 = p3.x * gB.z, w7 = p3.y * gB.w;
        *(float4*)&W[offA] = make_float4(w0, w1, w2, w3);
        *(float4*)&W[offB] = make_float4(w4, w5, w6, w7);
        rs[i] = ((w0 + w1) + (w2 + w3)) + ((w4 + w5) + (w6 + w7));
        mx[i] = fmaxf(fmaxf(fmaxf(w0, w1), fmaxf(w2, w3)), fmaxf(fmaxf(w4, w5), fmaxf(w6, w7)));
        mn[i] = fminf(fminf(fminf(w0, w1), fminf(w2, w3)), fminf(fminf(w4, w5), fminf(w6, w7)));
    }
#pragma unroll
    for (int off = 8; off; off >>= 1) {
#pragma unroll
        for (int i = 0; i < 8; i++) {
            rs[i] += __shfl_xor_sync(~0u, rs[i], off);
            mx[i] = fmaxf(mx[i], __shfl_xor_sync(~0u, mx[i], off));
            mn[i] = fminf(mn[i], __shfl_xor_sync(~0u, mn[i], off));
        }
    }
    if (tx == 0) {
#pragma unroll
        for (int i = 0; i < 8; i++) {
            int row = g * SEQ + i0 + (ty << 2) + (i & 3) + ((i >> 2) << 6);
            atomicAdd(&rsum[row], rs[i]);
            atomicMaxF(&rmax[row], mx[i]);
            atomicMinF(&rmin[row], mn[i]);
        }
    }
}

__global__ void init_stats(float* rsum, float* rmax, float* rmin) {
    int i = blockIdx.x * blockDim.x + threadIdx.x;
    if (i < GH * SEQ) { rsum[i] = 0.f; rmax[i] = -FLT_MAX; rmin[i] = FLT_MAX; }
}

// ---------------- exp pass: W <- exp(W/s - m), per-row Z ----------------
__global__ void softmax_exp_kernel(float* __restrict__ W, const float* __restrict__ rsum,
                                   const float* __restrict__ rmax, const float* __restrict__ rmin,
                                   float* __restrict__ Z) {
    int row = blockIdx.x;
    float s = rsum[row] + 1e-12f;
    float inv = 1.f / s;
    float m = (s > 0.f) ? rmax[row] * inv : rmin[row] * inv;
    float* Wr = W + (size_t)row * SEQ;
    float z = 0.f;
#pragma unroll
    for (int k = 0; k < 8; k++) {
        int j = threadIdx.x + (k << 8);
        float p = expf(Wr[j] * inv - m);
        Wr[j] = p;
        z += p;
    }
#pragma unroll
    for (int off = 16; off; off >>= 1) z += __shfl_xor_sync(~0u, z, off);
    __shared__ float sm[8];
    if ((threadIdx.x & 31) == 0) sm[threadIdx.x >> 5] = z;
    __syncthreads();
    if (threadIdx.x == 0) {
        float t = 0.f;
#pragma unroll
        for (int i = 0; i < 8; i++) t += sm[i];
        Z[row] = t;
    }
}

// ---------------- head-averaged attn weights out ----------------
__global__ void avgw_kernel(const float* __restrict__ P, const float* __restrict__ Z,
                            float* __restrict__ out) {
    int i = blockIdx.x, b = blockIdx.y;
    float iz[8];
#pragma unroll
    for (int h = 0; h < 8; h++) iz[h] = 0.125f / Z[(b * 8 + h) * SEQ + i];
    size_t obase = (size_t)b * SEQ * SEQ + (size_t)i * SEQ;
#pragma unroll
    for (int k = 0; k < 8; k++) {
        int j = threadIdx.x + (k << 8);
        float a = 0.f;
#pragma unroll
        for (int h = 0; h < 8; h++)
            a += P[(size_t)(b * 8 + h) * SEQ * SEQ + (size_t)i * SEQ + j] * iz[h];
        out[obase + j] = a;
    }
}

// ======== PV: Oc[(b,s),h*64+d] = sum_k P[g,s,k] V[g,k,d] / Z  (fused gather) ========
__global__ __launch_bounds__(128, 4)
void pv_kernel(const float* __restrict__ P, const float* __restrict__ V,
               const float* __restrict__ Z, float* __restrict__ Oc) {
    __shared__ __align__(16) float Ps[16][132];
    __shared__ __align__(16) float Vs[16][68];
    const int g = blockIdx.y;
    const int m0 = blockIdx.x << 7;
    const int tid = threadIdx.x;
    const int tx = tid & 7, ty = tid >> 3;   // tx 0..7 cols, ty 0..15 rows
    const int lr = tid >> 2;                  // 0..31
    const int lc = (tid & 3) << 2;
    const int vr = tid >> 4;                  // 0..7
    const int vc = (tid & 15) << 2;
    const float* Pg = P + (size_t)g * SEQ * SEQ;
    const float* Vg = V + (size_t)g * SEQ * DH;
    u64 acc[8][4];
#pragma unroll
    for (int i = 0; i < 8; i++)
#pragma unroll
        for (int j = 0; j < 4; j++) acc[i][j] = 0ull;

    for (int k0 = 0; k0 < SEQ; k0 += 16) {
        float4 p0 = *(const float4*)&Pg[(size_t)(m0 + lr)      * SEQ + k0 + lc];
        float4 p1 = *(const float4*)&Pg[(size_t)(m0 + 32 + lr) * SEQ + k0 + lc];
        float4 p2 = *(const float4*)&Pg[(size_t)(m0 + 64 + lr) * SEQ + k0 + lc];
        float4 p3 = *(const float4*)&Pg[(size_t)(m0 + 96 + lr) * SEQ + k0 + lc];
        float4 v0 = *(const float4*)&Vg[(size_t)(k0 + vr)     * DH + vc];
        float4 v1 = *(const float4*)&Vg[(size_t)(k0 + 8 + vr) * DH + vc];
        __syncthreads();
        Ps[lc + 0][lr] = p0.x; Ps[lc + 1][lr] = p0.y; Ps[lc + 2][lr] = p0.z; Ps[lc + 3][lr] = p0.w;
        Ps[lc + 0][32 + lr] = p1.x; Ps[lc + 1][32 + lr] = p1.y; Ps[lc + 2][32 + lr] = p1.z; Ps[lc + 3][32 + lr] = p1.w;
        Ps[lc + 0][64 + lr] = p2.x; Ps[lc + 1][64 + lr] = p2.y; Ps[lc + 2][64 + lr] = p2.z; Ps[lc + 3][64 + lr] = p2.w;
        Ps[lc + 0][96 + lr] = p3.x; Ps[lc + 1][96 + lr] = p3.y; Ps[lc + 2][96 + lr] = p3.z; Ps[lc + 3][96 + lr] = p3.w;
        *(float4*)&Vs[vr][vc] = v0;
        *(float4*)&Vs[8 + vr][vc] = v1;
        __syncthreads();
#pragma unroll
        for (int k = 0; k < 16; k++) {
            float4 af0 = *(const float4*)&Ps[k][ty << 2];
            float4 af1 = *(const float4*)&Ps[k][64 + (ty << 2)];
            ulonglong2 bp0 = *(const ulonglong2*)&Vs[k][tx << 2];
            ulonglong2 bp1 = *(const ulonglong2*)&Vs[k][32 + (tx << 2)];
            u64 ad[8] = { dup2(af0.x), dup2(af0.y), dup2(af0.z), dup2(af0.w),
                          dup2(af1.x), dup2(af1.y), dup2(af1.z), dup2(af1.w) };
            u64 bb[4] = { bp0.x, bp0.y, bp1.x, bp1.y };
#pragma unroll
            for (int i = 0; i < 8; i++) {
                ffma2(acc[i][0], ad[i], bb[0]);
                ffma2(acc[i][1], ad[i], bb[1]);
                ffma2(acc[i][2], ad[i], bb[2]);
                ffma2(acc[i][3], ad[i], bb[3]);
            }
        }
    }
    const int b = g >> 3, h = g & 7;
    float* ocb = Oc + (size_t)b * SEQ * EMB + h * 64;
#pragma unroll
    for (int i = 0; i < 8; i++) {
        int row = m0 + (ty << 2) + (i & 3) + ((i >> 2) << 6);
        float izv = 1.f / Z[g * SEQ + row];
        float* orow = ocb + (size_t)row * EMB;
#pragma unroll
        for (int jj = 0; jj < 4; jj++) {
            float2 v2 = unp(acc[i][jj]);
            int col = (tx << 2) + ((jj & 1) << 1) + ((jj >> 1) << 5);
            orow[col]     = v2.x * izv;
            orow[col + 1] = v2.y * izv;
        }
    }
}

// ---------------- launcher ----------------
extern "C" void kernel_launch(void* const* d_in, const int* in_sizes, int n_in,
                              void* d_out, int out_size) {
    const float* query = (const float*)d_in[0];
    const float* gate  = (const float*)d_in[1];
    const float* ipw   = (const float*)d_in[2];
    const float* ipb   = (const float*)d_in[3];
    const float* outw  = (const float*)d_in[4];
    const float* outb  = (const float*)d_in[5];
    const float* ln1w  = (const float*)d_in[6];
    const float* ln1b  = (const float*)d_in[7];
    const float* ln2w  = (const float*)d_in[8];
    const float* ln2b  = (const float*)d_in[9];
    const float* w1    = (const float*)d_in[10];
    const float* b1    = (const float*)d_in[11];
    const float* w2    = (const float*)d_in[12];
    const float* b2    = (const float*)d_in[13];
    float* out_x = (float*)d_out;
    float* out_w = out_x + (size_t)2 * SEQ * EMB;

    float *p_nq, *p_q, *p_k, *p_v, *p_W, *p_rsum, *p_rmax, *p_rmin, *p_Z;
    float *p_Oc, *p_x, *p_h, *p_mlp;
    cudaGetSymbolAddress((void**)&p_nq,  g_nq);
    cudaGetSymbolAddress((void**)&p_q,   g_q);
    cudaGetSymbolAddress((void**)&p_k,   g_k);
    cudaGetSymbolAddress((void**)&p_v,   g_v);
    cudaGetSymbolAddress((void**)&p_W,   g_W);
    cudaGetSymbolAddress((void**)&p_rsum,g_rsum);
    cudaGetSymbolAddress((void**)&p_rmax,g_rmax);
    cudaGetSymbolAddress((void**)&p_rmin,g_rmin);
    cudaGetSymbolAddress((void**)&p_Z,   g_Z);
    cudaGetSymbolAddress((void**)&p_Oc,  g_Oc);
    cudaGetSymbolAddress((void**)&p_x,   g_x);
    cudaGetSymbolAddress((void**)&p_h,   g_h);
    cudaGetSymbolAddress((void**)&p_mlp, g_mlp);

    init_stats<<<(GH * SEQ + 255) / 256, 256>>>(p_rsum, p_rmax, p_rmin);
    ln_kernel<<<MR, 256>>>(query, ln1w, ln1b, p_nq);
    sgemm128<0><<<dim3(12, 32), 256>>>(p_nq, ipw, ipb, nullptr, p_q, p_k, p_v, MR, 1536, EMB);
    scores_kernel<<<dim3(16, 16, GH), 256>>>(p_q, p_k, gate, p_W, p_rsum, p_rmax, p_rmin);
    softmax_exp_kernel<<<GH * SEQ, 256>>>(p_W, p_rsum, p_rmax, p_rmin, p_Z);
    avgw_kernel<<<dim3(SEQ, 2), 256>>>(p_W, p_Z, out_w);
    pv_kernel<<<dim3(16, GH), 128>>>(p_W, p_v, p_Z, p_Oc);
    sgemm128<1><<<dim3(4, 32), 256>>>(p_Oc, outw, outb, query, p_x, nullptr, nullptr, MR, EMB, EMB);
    ln_kernel<<<MR, 256>>>(p_x, ln2w, ln2b, p_h);
    sgemm128<2><<<dim3(16, 32), 256>>>(p_h, w1, b1, nullptr, p_mlp, nullptr, nullptr, MR, MLPD, EMB);
    sgemm128<1><<<dim3(4, 32), 256>>>(p_mlp, w2, b2, p_x, out_x, nullptr, nullptr, MR, EMB, MLPD);
}

// round 4
// speedup vs baseline: 1.4650x; 1.0246x over previous
#include <cuda_runtime.h>
#include <math.h>
#include <float.h>
#include <stdint.h>

// Problem constants
#define GH   16        // B*H groups
#define SEQ  2048
#define EMB  512
#define DH   64
#define MR   4096      // B*S rows
#define MLPD 2048

typedef unsigned long long u64;

// ---------------- scratch (static device globals; no allocation) ----------------
__device__ float g_nq [MR*EMB];
__device__ float g_q  [MR*EMB];
__device__ float g_k  [MR*EMB];
__device__ float g_v  [MR*EMB];
__device__ float g_W  [(size_t)GH*SEQ*SEQ];     // 256MB: scores -> exp(p) in place
__device__ float g_rsum[GH*SEQ];
__device__ float g_rmax[GH*SEQ];
__device__ float g_rmin[GH*SEQ];
__device__ float g_Z  [GH*SEQ];
__device__ float g_Oc [MR*EMB];
__device__ float g_x  [MR*EMB];
__device__ float g_h  [MR*EMB];
__device__ float g_mlp[(size_t)MR*MLPD];

// ---------------- packed f32x2 helpers (scalar kernels) ----------------
__device__ __forceinline__ u64 dup2(float a) {
    u64 r; asm("mov.b64 %0, {%1,%1};" : "=l"(r) : "f"(a)); return r;
}
__device__ __forceinline__ void ffma2(u64& d, u64 a, u64 b) {
    asm("fma.rn.f32x2 %0, %1, %2, %0;" : "+l"(d) : "l"(a), "l"(b));
}
__device__ __forceinline__ float2 unp(u64 v) {
    float2 r; asm("mov.b64 {%0,%1}, %2;" : "=f"(r.x), "=f"(r.y) : "l"(v)); return r;
}

__device__ __forceinline__ void atomicMaxF(float* addr, float val) {
    int old = __float_as_int(*addr);
    while (__int_as_float(old) < val) {
        int assumed = old;
        old = atomicCAS((int*)addr, assumed, __float_as_int(val));
        if (old == assumed) break;
    }
}
__device__ __forceinline__ void atomicMinF(float* addr, float val) {
    int old = __float_as_int(*addr);
    while (__int_as_float(old) > val) {
        int assumed = old;
        old = atomicCAS((int*)addr, assumed, __float_as_int(val));
        if (old == assumed) break;
    }
}

// ---------------- tf32 helpers ----------------
__device__ __forceinline__ float tf32r(float x) {
    uint32_t r; asm("cvt.rna.tf32.f32 %0, %1;" : "=r"(r) : "f"(x));
    return __uint_as_float(r);
}
__device__ __forceinline__ void mma8(float* c, const uint32_t* a, const uint32_t* b) {
    asm volatile(
        "mma.sync.aligned.m16n8k8.row.col.f32.tf32.tf32.f32 "
        "{%0,%1,%2,%3}, {%4,%5,%6,%7}, {%8,%9}, {%0,%1,%2,%3};"
        : "+f"(c[0]), "+f"(c[1]), "+f"(c[2]), "+f"(c[3])
        : "r"(a[0]), "r"(a[1]), "r"(a[2]), "r"(a[3]), "r"(b[0]), "r"(b[1]));
}

// ======== mma.sync tf32 3x-split GEMM: C[m,n] = sum_k A[m,k]*B[n,k] + bias ========
// Block 128x128, 8 warps (2m x 4n), warp tile 64x32. K chunks of 32.
// EPI 0: qkv split; 1: +residual; 2: exact gelu.
#define MM_PAD   36
#define MM_ARR   (128 * MM_PAD)                    // floats per smem matrix
#define MM_SMEM  (4 * MM_ARR * 4)                  // Ah, Al, Bh, Bl = 73728 B

template <int EPI>
__global__ __launch_bounds__(256, 2)
void sgemm_mma(const float* __restrict__ A, const float* __restrict__ B,
               const float* __restrict__ bias, const float* __restrict__ res,
               float* __restrict__ C0, float* __restrict__ C1, float* __restrict__ C2,
               int N, int K) {
    extern __shared__ __align__(16) float sm[];
    float* sAh = sm;
    float* sAl = sm + 1 * MM_ARR;
    float* sBh = sm + 2 * MM_ARR;
    float* sBl = sm + 3 * MM_ARR;

    const int tid = threadIdx.x;
    const int wid = tid >> 5, lid = tid & 31;
    const int g = lid >> 2, t4 = lid & 3;
    const int wm = (wid >> 2) << 6;      // 0 or 64
    const int wn = (wid & 3) << 5;       // 0,32,64,96
    const int m0 = blockIdx.y << 7, n0 = blockIdx.x << 7;
    const int nc = K >> 5;

    // gmem load mapping: 2 threads per row, 16 floats each
    const int lrow = tid >> 1;
    const int lkb  = (tid & 1) << 4;
    const float* Arow = A + (size_t)(m0 + lrow) * K + lkb;
    const float* Brow = B + (size_t)(n0 + lrow) * K + lkb;

    float4 ra[4], rb[4];
    auto load_regs = [&](int c) {
        const int kc = c << 5;
#pragma unroll
        for (int i = 0; i < 4; i++) {
            ra[i] = *(const float4*)(Arow + kc + (i << 2));
            rb[i] = *(const float4*)(Brow + kc + (i << 2));
        }
    };
    auto store_smem = [&]() {
        const int base = lrow * MM_PAD + lkb;
#pragma unroll
        for (int i = 0; i < 4; i++) {
            float4 a = ra[i], b = rb[i];
            float4 ah, al, bh, bl;
            ah.x = tf32r(a.x); al.x = tf32r(a.x - ah.x);
            ah.y = tf32r(a.y); al.y = tf32r(a.y - ah.y);
            ah.z = tf32r(a.z); al.z = tf32r(a.z - ah.z);
            ah.w = tf32r(a.w); al.w = tf32r(a.w - ah.w);
            bh.x = tf32r(b.x); bl.x = tf32r(b.x - bh.x);
            bh.y = tf32r(b.y); bl.y = tf32r(b.y - bh.y);
            bh.z = tf32r(b.z); bl.z = tf32r(b.z - bh.z);
            bh.w = tf32r(b.w); bl.w = tf32r(b.w - bh.w);
            *(float4*)&sAh[base + (i << 2)] = ah;
            *(float4*)&sAl[base + (i << 2)] = al;
            *(float4*)&sBh[base + (i << 2)] = bh;
            *(float4*)&sBl[base + (i << 2)] = bl;
        }
    };

    float acc[4][4][4];
#pragma unroll
    for (int mi = 0; mi < 4; mi++)
#pragma unroll
        for (int ni = 0; ni < 4; ni++)
#pragma unroll
            for (int f = 0; f < 4; f++) acc[mi][ni][f] = 0.f;

    load_regs(0);
    store_smem();
    __syncthreads();

    for (int c = 0; c < nc; c++) {
        if (c + 1 < nc) load_regs(c + 1);
#pragma unroll
        for (int ki = 0; ki < 4; ki++) {
            const int kc = (ki << 3) + t4;
            uint32_t bh[4][2], bl[4][2];
#pragma unroll
            for (int ni = 0; ni < 4; ni++) {
                const int nn = (wn + (ni << 3) + g) * MM_PAD;
                bh[ni][0] = __float_as_uint(sBh[nn + kc]);
                bh[ni][1] = __float_as_uint(sBh[nn + kc + 4]);
                bl[ni][0] = __float_as_uint(sBl[nn + kc]);
                bl[ni][1] = __float_as_uint(sBl[nn + kc + 4]);
            }
#pragma unroll
            for (int mi = 0; mi < 4; mi++) {
                const int r0 = (wm + (mi << 4) + g) * MM_PAD;
                const int r8 = r0 + (MM_PAD << 3);
                uint32_t ah[4], al[4];
                ah[0] = __float_as_uint(sAh[r0 + kc]);
                ah[1] = __float_as_uint(sAh[r8 + kc]);
                ah[2] = __float_as_uint(sAh[r0 + kc + 4]);
                ah[3] = __float_as_uint(sAh[r8 + kc + 4]);
                al[0] = __float_as_uint(sAl[r0 + kc]);
                al[1] = __float_as_uint(sAl[r8 + kc]);
                al[2] = __float_as_uint(sAl[r0 + kc + 4]);
                al[3] = __float_as_uint(sAl[r8 + kc + 4]);
#pragma unroll
                for (int ni = 0; ni < 4; ni++) {
                    mma8(acc[mi][ni], ah, bh[ni]);
                    mma8(acc[mi][ni], ah, bl[ni]);
                    mma8(acc[mi][ni], al, bh[ni]);
                }
            }
        }
        __syncthreads();
        if (c + 1 < nc) {
            store_smem();
            __syncthreads();
        }
    }

    // epilogue: thread owns pairs (r, cn),(r, cn+1) and (r+8, cn),(r+8, cn+1) per (mi,ni)
    auto epi2 = [&](int row, int col, float v0, float v1) {
        v0 += bias[col]; v1 += bias[col + 1];
        if (EPI == 0) {
            float* dst = (col < 512) ? C0 : ((col < 1024) ? C1 : C2);
            float2 o = make_float2(v0, v1);
            *(float2*)&dst[(size_t)row * 512 + (col & 511)] = o;
        } else if (EPI == 1) {
            float2 rv = *(const float2*)&res[(size_t)row * N + col];
            *(float2*)&C0[(size_t)row * N + col] = make_float2(v0 + rv.x, v1 + rv.y);
        } else {
            float2 o;
            o.x = 0.5f * v0 * (1.f + erff(v0 * 0.7071067811865475f));
            o.y = 0.5f * v1 * (1.f + erff(v1 * 0.7071067811865475f));
            *(float2*)&C0[(size_t)row * N + col] = o;
        }
    };
#pragma unroll
    for (int mi = 0; mi < 4; mi++) {
        const int r = m0 + wm + (mi << 4) + g;
#pragma unroll
        for (int ni = 0; ni < 4; ni++) {
            const int cn = n0 + wn + (ni << 3) + (t4 << 1);
            epi2(r,     cn, acc[mi][ni][0], acc[mi][ni][1]);
            epi2(r + 8, cn, acc[mi][ni][2], acc[mi][ni][3]);
        }
    }
}

// ---------------- LayerNorm (1 block / row of 512) ----------------
__global__ void ln_kernel(const float* __restrict__ x, const float* __restrict__ w,
                          const float* __restrict__ b, float* __restrict__ y) {
    int row = blockIdx.x;
    const float* xr = x + (size_t)row * EMB;
    int t = threadIdx.x;
    float v0 = xr[t], v1 = xr[t + 256];
    float s = v0 + v1, q = v0 * v0 + v1 * v1;
#pragma unroll
    for (int off = 16; off; off >>= 1) {
        s += __shfl_xor_sync(~0u, s, off);
        q += __shfl_xor_sync(~0u, q, off);
    }
    __shared__ float ss[8], sq[8];
    if ((t & 31) == 0) { ss[t >> 5] = s; sq[t >> 5] = q; }
    __syncthreads();
    if (t == 0) {
        float s2 = 0.f, q2 = 0.f;
#pragma unroll
        for (int i = 0; i < 8; i++) { s2 += ss[i]; q2 += sq[i]; }
        ss[0] = s2; sq[0] = q2;
    }
    __syncthreads();
    float mean = ss[0] * (1.f / EMB);
    float var  = sq[0] * (1.f / EMB) - mean * mean;
    float rstd = rsqrtf(var + 1e-5f);
    float* yr = y + (size_t)row * EMB;
    yr[t]       = (v0 - mean) * rstd * w[t]       + b[t];
    yr[t + 256] = (v1 - mean) * rstd * w[t + 256] + b[t + 256];
}

// ======== scores: W = (Q K^T) * gate, 128x128 tile, FFMA2, row stats ========
__global__ __launch_bounds__(256, 2)
void scores_kernel(const float* __restrict__ Q, const float* __restrict__ Km,
                   const float* __restrict__ gate, float* __restrict__ W,
                   float* __restrict__ rsum, float* __restrict__ rmax,
                   float* __restrict__ rmin) {
    __shared__ __align__(16) float As[16][132];
    __shared__ __align__(16) float Bs[16][132];
    const int g = blockIdx.z;
    const int tid = threadIdx.x;
    const int tx = tid & 15, ty = tid >> 4;
    const int i0 = blockIdx.y << 7, j0 = blockIdx.x << 7;
    const int lr = tid >> 2;
    const int lc = (tid & 3) << 2;
    const float* Qg = Q + (size_t)g * SEQ * DH;
    const float* Kg = Km + (size_t)g * SEQ * DH;
    const float* Ap0 = Qg + (size_t)(i0 + lr) * DH + lc;
    const float* Ap1 = Qg + (size_t)(i0 + 64 + lr) * DH + lc;
    const float* Bp0 = Kg + (size_t)(j0 + lr) * DH + lc;
    const float* Bp1 = Kg + (size_t)(j0 + 64 + lr) * DH + lc;
    u64 acc[8][4];
#pragma unroll
    for (int i = 0; i < 8; i++)
#pragma unroll
        for (int j = 0; j < 4; j++) acc[i][j] = 0ull;

    for (int k0 = 0; k0 < DH; k0 += 16) {
        float4 a0 = *(const float4*)(Ap0 + k0);
        float4 a1 = *(const float4*)(Ap1 + k0);
        float4 b0 = *(const float4*)(Bp0 + k0);
        float4 b1 = *(const float4*)(Bp1 + k0);
        __syncthreads();
        As[lc + 0][lr] = a0.x; As[lc + 1][lr] = a0.y; As[lc + 2][lr] = a0.z; As[lc + 3][lr] = a0.w;
        As[lc + 0][64 + lr] = a1.x; As[lc + 1][64 + lr] = a1.y; As[lc + 2][64 + lr] = a1.z; As[lc + 3][64 + lr] = a1.w;
        Bs[lc + 0][lr] = b0.x; Bs[lc + 1][lr] = b0.y; Bs[lc + 2][lr] = b0.z; Bs[lc + 3][lr] = b0.w;
        Bs[lc + 0][64 + lr] = b1.x; Bs[lc + 1][64 + lr] = b1.y; Bs[lc + 2][64 + lr] = b1.z; Bs[lc + 3][64 + lr] = b1.w;
        __syncthreads();
#pragma unroll
        for (int k = 0; k < 16; k++) {
            float4 af0 = *(const float4*)&As[k][ty << 2];
            float4 af1 = *(const float4*)&As[k][64 + (ty << 2)];
            ulonglong2 bp0 = *(const ulonglong2*)&Bs[k][tx << 2];
            ulonglong2 bp1 = *(const ulonglong2*)&Bs[k][64 + (tx << 2)];
            u64 ad[8] = { dup2(af0.x), dup2(af0.y), dup2(af0.z), dup2(af0.w),
                          dup2(af1.x), dup2(af1.y), dup2(af1.z), dup2(af1.w) };
            u64 bb[4] = { bp0.x, bp0.y, bp1.x, bp1.y };
#pragma unroll
            for (int i = 0; i < 8; i++) {
                ffma2(acc[i][0], ad[i], bb[0]);
                ffma2(acc[i][1], ad[i], bb[1]);
                ffma2(acc[i][2], ad[i], bb[2]);
                ffma2(acc[i][3], ad[i], bb[3]);
            }
        }
    }

    float rs[8], mx[8], mn[8];
    size_t wbase = (size_t)g * SEQ * SEQ;
#pragma unroll
    for (int i = 0; i < 8; i++) {
        int row = i0 + (ty << 2) + (i & 3) + ((i >> 2) << 6);
        float2 p0 = unp(acc[i][0]), p1 = unp(acc[i][1]);
        float2 p2 = unp(acc[i][2]), p3 = unp(acc[i][3]);
        size_t offA = wbase + (size_t)row * SEQ + j0 + (tx << 2);
        size_t offB = offA + 64;
        float4 gA = *(const float4*)&gate[offA];
        float4 gB = *(const float4*)&gate[offB];
        float w0 = p0.x * gA.x, w1 = p0.y * gA.y, w2 = p1.x * gA.z, w3 = p1.y * gA.w;
        float w4 = p2.x * gB.x, w5 = p2.y * gB.y, w6 = p3.x * gB.z, w7 = p3.y * gB.w;
        *(float4*)&W[offA] = make_float4(w0, w1, w2, w3);
        *(float4*)&W[offB] = make_float4(w4, w5, w6, w7);
        rs[i] = ((w0 + w1) + (w2 + w3)) + ((w4 + w5) + (w6 + w7));
        mx[i] = fmaxf(fmaxf(fmaxf(w0, w1), fmaxf(w2, w3)), fmaxf(fmaxf(w4, w5), fmaxf(w6, w7)));
        mn[i] = fminf(fminf(fminf(w0, w1), fminf(w2, w3)), fminf(fminf(w4, w5), fminf(w6, w7)));
    }
#pragma unroll
    for (int off = 8; off; off >>= 1) {
#pragma unroll
        for (int i = 0; i < 8; i++) {
            rs[i] += __shfl_xor_sync(~0u, rs[i], off);
            mx[i] = fmaxf(mx[i], __shfl_xor_sync(~0u, mx[i], off));
            mn[i] = fminf(mn[i], __shfl_xor_sync(~0u, mn[i], off));
        }
    }
    if (tx == 0) {
#pragma unroll
        for (int i = 0; i < 8; i++) {
            int row = g * SEQ + i0 + (ty << 2) + (i & 3) + ((i >> 2) << 6);
            atomicAdd(&rsum[row], rs[i]);
            atomicMaxF(&rmax[row], mx[i]);
            atomicMinF(&rmin[row], mn[i]);
        }
    }
}

__global__ void init_stats(float* rsum, float* rmax, float* rmin) {
    int i = blockIdx.x * blockDim.x + threadIdx.x;
    if (i < GH * SEQ) { rsum[i] = 0.f; rmax[i] = -FLT_MAX; rmin[i] = FLT_MAX; }
}

// ---------------- exp pass: W <- exp(W/s - m), per-row Z ----------------
__global__ void softmax_exp_kernel(float* __restrict__ W, const float* __restrict__ rsum,
                                   const float* __restrict__ rmax, const float* __restrict__ rmin,
                                   float* __restrict__ Z) {
    int row = blockIdx.x;
    float s = rsum[row] + 1e-12f;
    float inv = 1.f / s;
    float m = (s > 0.f) ? rmax[row] * inv : rmin[row] * inv;
    float* Wr = W + (size_t)row * SEQ;
    float z = 0.f;
#pragma unroll
    for (int k = 0; k < 8; k++) {
        int j = threadIdx.x + (k << 8);
        float p = expf(Wr[j] * inv - m);
        Wr[j] = p;
        z += p;
    }
#pragma unroll
    for (int off = 16; off; off >>= 1) z += __shfl_xor_sync(~0u, z, off);
    __shared__ float sm2[8];
    if ((threadIdx.x & 31) == 0) sm2[threadIdx.x >> 5] = z;
    __syncthreads();
    if (threadIdx.x == 0) {
        float t = 0.f;
#pragma unroll
        for (int i = 0; i < 8; i++) t += sm2[i];
        Z[row] = t;
    }
}

// ---------------- head-averaged attn weights out ----------------
__global__ void avgw_kernel(const float* __restrict__ P, const float* __restrict__ Z,
                            float* __restrict__ out) {
    int i = blockIdx.x, b = blockIdx.y;
    float iz[8];
#pragma unroll
    for (int h = 0; h < 8; h++) iz[h] = 0.125f / Z[(b * 8 + h) * SEQ + i];
    size_t obase = (size_t)b * SEQ * SEQ + (size_t)i * SEQ;
#pragma unroll
    for (int k = 0; k < 8; k++) {
        int j = threadIdx.x + (k << 8);
        float a = 0.f;
#pragma unroll
        for (int h = 0; h < 8; h++)
            a += P[(size_t)(b * 8 + h) * SEQ * SEQ + (size_t)i * SEQ + j] * iz[h];
        out[obase + j] = a;
    }
}

// ======== PV: Oc[(b,s),h*64+d] = sum_k P[g,s,k] V[g,k,d] / Z  (fused gather) ========
__global__ __launch_bounds__(128, 4)
void pv_kernel(const float* __restrict__ P, const float* __restrict__ V,
               const float* __restrict__ Z, float* __restrict__ Oc) {
    __shared__ __align__(16) float Ps[16][132];
    __shared__ __align__(16) float Vs[16][68];
    const int g = blockIdx.y;
    const int m0 = blockIdx.x << 7;
    const int tid = threadIdx.x;
    const int tx = tid & 7, ty = tid >> 3;
    const int lr = tid >> 2;
    const int lc = (tid & 3) << 2;
    const int vr = tid >> 4;
    const int vc = (tid & 15) << 2;
    const float* Pg = P + (size_t)g * SEQ * SEQ;
    const float* Vg = V + (size_t)g * SEQ * DH;
    u64 acc[8][4];
#pragma unroll
    for (int i = 0; i < 8; i++)
#pragma unroll
        for (int j = 0; j < 4; j++) acc[i][j] = 0ull;

    for (int k0 = 0; k0 < SEQ; k0 += 16) {
        float4 p0 = *(const float4*)&Pg[(size_t)(m0 + lr)      * SEQ + k0 + lc];
        float4 p1 = *(const float4*)&Pg[(size_t)(m0 + 32 + lr) * SEQ + k0 + lc];
        float4 p2 = *(const float4*)&Pg[(size_t)(m0 + 64 + lr) * SEQ + k0 + lc];
        float4 p3 = *(const float4*)&Pg[(size_t)(m0 + 96 + lr) * SEQ + k0 + lc];
        float4 v0 = *(const float4*)&Vg[(size_t)(k0 + vr)     * DH + vc];
        float4 v1 = *(const float4*)&Vg[(size_t)(k0 + 8 + vr) * DH + vc];
        __syncthreads();
        Ps[lc + 0][lr] = p0.x; Ps[lc + 1][lr] = p0.y; Ps[lc + 2][lr] = p0.z; Ps[lc + 3][lr] = p0.w;
        Ps[lc + 0][32 + lr] = p1.x; Ps[lc + 1][32 + lr] = p1.y; Ps[lc + 2][32 + lr] = p1.z; Ps[lc + 3][32 + lr] = p1.w;
        Ps[lc + 0][64 + lr] = p2.x; Ps[lc + 1][64 + lr] = p2.y; Ps[lc + 2][64 + lr] = p2.z; Ps[lc + 3][64 + lr] = p2.w;
        Ps[lc + 0][96 + lr] = p3.x; Ps[lc + 1][96 + lr] = p3.y; Ps[lc + 2][96 + lr] = p3.z; Ps[lc + 3][96 + lr] = p3.w;
        *(float4*)&Vs[vr][vc] = v0;
        *(float4*)&Vs[8 + vr][vc] = v1;
        __syncthreads();
#pragma unroll
        for (int k = 0; k < 16; k++) {
            float4 af0 = *(const float4*)&Ps[k][ty << 2];
            float4 af1 = *(const float4*)&Ps[k][64 + (ty << 2)];
            ulonglong2 bp0 = *(const ulonglong2*)&Vs[k][tx << 2];
            ulonglong2 bp1 = *(const ulonglong2*)&Vs[k][32 + (tx << 2)];
            u64 ad[8] = { dup2(af0.x), dup2(af0.y), dup2(af0.z), dup2(af0.w),
                          dup2(af1.x), dup2(af1.y), dup2(af1.z), dup2(af1.w) };
            u64 bb[4] = { bp0.x, bp0.y, bp1.x, bp1.y };
#pragma unroll
            for (int i = 0; i < 8; i++) {
                ffma2(acc[i][0], ad[i], bb[0]);
                ffma2(acc[i][1], ad[i], bb[1]);
                ffma2(acc[i][2], ad[i], bb[2]);
                ffma2(acc[i][3], ad[i], bb[3]);
            }
        }
    }
    const int b = g >> 3, h = g & 7;
    float* ocb = Oc + (size_t)b * SEQ * EMB + h * 64;
#pragma unroll
    for (int i = 0; i < 8; i++) {
        int row = m0 + (ty << 2) + (i & 3) + ((i >> 2) << 6);
        float izv = 1.f / Z[g * SEQ + row];
        float* orow = ocb + (size_t)row * EMB;
#pragma unroll
        for (int jj = 0; jj < 4; jj++) {
            float2 v2 = unp(acc[i][jj]);
            int col = (tx << 2) + ((jj & 1) << 1) + ((jj >> 1) << 5);
            orow[col]     = v2.x * izv;
            orow[col + 1] = v2.y * izv;
        }
    }
}

// ---------------- launcher ----------------
extern "C" void kernel_launch(void* const* d_in, const int* in_sizes, int n_in,
                              void* d_out, int out_size) {
    const float* query = (const float*)d_in[0];
    const float* gate  = (const float*)d_in[1];
    const float* ipw   = (const float*)d_in[2];
    const float* ipb   = (const float*)d_in[3];
    const float* outw  = (const float*)d_in[4];
    const float* outb  = (const float*)d_in[5];
    const float* ln1w  = (const float*)d_in[6];
    const float* ln1b  = (const float*)d_in[7];
    const float* ln2w  = (const float*)d_in[8];
    const float* ln2b  = (const float*)d_in[9];
    const float* w1    = (const float*)d_in[10];
    const float* b1    = (const float*)d_in[11];
    const float* w2    = (const float*)d_in[12];
    const float* b2    = (const float*)d_in[13];
    float* out_x = (float*)d_out;
    float* out_w = out_x + (size_t)2 * SEQ * EMB;

    float *p_nq, *p_q, *p_k, *p_v, *p_W, *p_rsum, *p_rmax, *p_rmin, *p_Z;
    float *p_Oc, *p_x, *p_h, *p_mlp;
    cudaGetSymbolAddress((void**)&p_nq,  g_nq);
    cudaGetSymbolAddress((void**)&p_q,   g_q);
    cudaGetSymbolAddress((void**)&p_k,   g_k);
    cudaGetSymbolAddress((void**)&p_v,   g_v);
    cudaGetSymbolAddress((void**)&p_W,   g_W);
    cudaGetSymbolAddress((void**)&p_rsum,g_rsum);
    cudaGetSymbolAddress((void**)&p_rmax,g_rmax);
    cudaGetSymbolAddress((void**)&p_rmin,g_rmin);
    cudaGetSymbolAddress((void**)&p_Z,   g_Z);
    cudaGetSymbolAddress((void**)&p_Oc,  g_Oc);
    cudaGetSymbolAddress((void**)&p_x,   g_x);
    cudaGetSymbolAddress((void**)&p_h,   g_h);
    cudaGetSymbolAddress((void**)&p_mlp, g_mlp);

    cudaFuncSetAttribute(sgemm_mma<0>, cudaFuncAttributeMaxDynamicSharedMemorySize, MM_SMEM);
    cudaFuncSetAttribute(sgemm_mma<1>, cudaFuncAttributeMaxDynamicSharedMemorySize, MM_SMEM);
    cudaFuncSetAttribute(sgemm_mma<2>, cudaFuncAttributeMaxDynamicSharedMemorySize, MM_SMEM);

    init_stats<<<(GH * SEQ + 255) / 256, 256>>>(p_rsum, p_rmax, p_rmin);
    ln_kernel<<<MR, 256>>>(query, ln1w, ln1b, p_nq);
    sgemm_mma<0><<<dim3(12, 32), 256, MM_SMEM>>>(p_nq, ipw, ipb, nullptr, p_q, p_k, p_v, 1536, EMB);
    scores_kernel<<<dim3(16, 16, GH), 256>>>(p_q, p_k, gate, p_W, p_rsum, p_rmax, p_rmin);
    softmax_exp_kernel<<<GH * SEQ, 256>>>(p_W, p_rsum, p_rmax, p_rmin, p_Z);
    avgw_kernel<<<dim3(SEQ, 2), 256>>>(p_W, p_Z, out_w);
    pv_kernel<<<dim3(16, GH), 128>>>(p_W, p_v, p_Z, p_Oc);
    sgemm_mma<1><<<dim3(4, 32), 256, MM_SMEM>>>(p_Oc, outw, outb, query, p_x, nullptr, nullptr, EMB, EMB);
    ln_kernel<<<MR, 256>>>(p_x, ln2w, ln2b, p_h);
    sgemm_mma<2><<<dim3(16, 32), 256, MM_SMEM>>>(p_h, w1, b1, nullptr, p_mlp, nullptr, nullptr, MLPD, EMB);
    sgemm_mma<1><<<dim3(4, 32), 256, MM_SMEM>>>(p_mlp, w2, b2, p_x, out_x, nullptr, nullptr, EMB, MLPD);
}